// round 7
// baseline (speedup 1.0000x reference)
#include <cuda_runtime.h>

#define B_G 4096
#define HID 32
#define FIN 64

typedef unsigned long long u64;

__device__ __forceinline__ u64 pack2(float a, float b) {
    u64 r; asm("mov.b64 %0, {%1, %2};" : "=l"(r) : "f"(a), "f"(b)); return r;
}
__device__ __forceinline__ void unpack2(float& a, float& b, u64 v) {
    asm("mov.b64 {%0, %1}, %2;" : "=f"(a), "=f"(b) : "l"(v));
}
__device__ __forceinline__ void fma2(u64& d, u64 a, u64 b) {
    asm("fma.rn.f32x2 %0, %1, %2, %0;" : "+l"(d) : "l"(a), "l"(b));
}
__device__ __forceinline__ u64 mul2(u64 a, u64 b) {
    u64 r; asm("mul.rn.f32x2 %0, %1, %2;" : "=l"(r) : "l"(a), "l"(b)); return r;
}
__device__ __forceinline__ u64 add2(u64 a, u64 b) {
    u64 r; asm("add.rn.f32x2 %0, %1, %2;" : "=l"(r) : "l"(a), "l"(b)); return r;
}

// dynamic smem layout (bytes)
#define HT_OFF     0         // hT: 32 rows x 384 floats (12-float lane groups) = 49152
#define W2_OFF     49152     // 4 KB
#define W1_OFF     53248     // 256 B
#define B1_OFF     53504     // 128 B
#define B2_OFF     53632     // 128 B
#define EA_OFF     53760     // 4 warps x 16 u64 = 512 B
#define EB_OFF     54272     // 512 B
#define PL_OFF     54784     // pooled, 128 B
#define SMEM_TOTAL 54912

__global__ __launch_bounds__(128, 4)
void snake_kernel(const float* __restrict__ x,
                  const float* __restrict__ heads,
                  const float* __restrict__ body_sizes,
                  const float* __restrict__ fruits,
                  const float* __restrict__ W1, const float* __restrict__ b1,
                  const float* __restrict__ W2, const float* __restrict__ b2,
                  const float* __restrict__ Wr, const float* __restrict__ br,
                  const float* __restrict__ Wa1, const float* __restrict__ ba1,
                  const float* __restrict__ Wa2, const float* __restrict__ ba2,
                  const float* __restrict__ Wc, const float* __restrict__ bc,
                  const float* __restrict__ Wp, const float* __restrict__ bp,
                  const float* __restrict__ Wv, const float* __restrict__ bv,
                  float* __restrict__ out)
{
    extern __shared__ __align__(16) char smem[];
    float* hT   = (float*)(smem + HT_OFF);
    float* sW2  = (float*)(smem + W2_OFF);
    float* sW1  = (float*)(smem + W1_OFF);
    float* sb1  = (float*)(smem + B1_OFF);
    float* sb2  = (float*)(smem + B2_OFF);
    u64*  edgeA = (u64*)(smem + EA_OFF);     // [warp][16]
    u64*  edgeB = (u64*)(smem + EB_OFF);
    float* pooledS = (float*)(smem + PL_OFF);

    const int b = blockIdx.x;
    const int t = threadIdx.x;
    const int lane = t & 31;
    const int w = t >> 5;

    // warp-0 prefetch of per-graph aux scalars (hide L2 latency behind main path)
    float ph0 = 0.f, ph1 = 0.f, pbs = 0.f, pf0 = 0.f, pf1 = 0.f;
    if (w == 0) {
        ph0 = heads[2 * b]; ph1 = heads[2 * b + 1];
        pbs = body_sizes[b];
        pf0 = fruits[2 * b]; pf1 = fruits[2 * b + 1];
    }

    // ---- weight staging ----
    ((float4*)sW2)[t] = ((const float4*)W2)[t];
    ((float4*)sW2)[t + 128] = ((const float4*)W2)[t + 128];
    if (t < 16) ((float4*)sW1)[t] = ((const float4*)W1)[t];
    else if (t < 24) ((float4*)sb1)[t - 16] = ((const float4*)b1)[t - 16];
    else if (t < 32) ((float4*)sb2)[t - 24] = ((const float4*)b2)[t - 24];

    const float4 xv = ((const float4*)x)[b * 128 + t];
    __syncthreads();                                        // barrier 1

    // ---------------- layer 1: y = x @ W1 (nodes 2t, 2t+1) ----------------
    float y0[HID], y1[HID];
    {
        const u64* w1a = (const u64*)sW1;
        const u64* w1b = (const u64*)(sW1 + HID);
        const u64 xa0 = pack2(xv.x, xv.x), xb0 = pack2(xv.y, xv.y);
        const u64 xa1 = pack2(xv.z, xv.z), xb1 = pack2(xv.w, xv.w);
#pragma unroll
        for (int p = 0; p < 16; p++) {
            const u64 wA = w1a[p], wB = w1b[p];
            u64 v0 = mul2(xa0, wA); fma2(v0, xb0, wB);
            u64 v1 = mul2(xa1, wA); fma2(v1, xb1, wB);
            unpack2(y0[2 * p], y0[2 * p + 1], v0);
            unpack2(y1[2 * p], y1[2 * p + 1], v1);
        }
    }

    // ---- stencil 1 weights (nodes 2t, 2t+1; L=256) ----
    const float rs2 = 0.70710678118654752440f;
    const float rs3 = 0.57735026918962576451f;
    const float dinv0 = (t == 0)   ? rs2 : rs3;
    const float dinv1 = (t == 127) ? rs2 : rs3;
    const float wc0 = dinv0 * dinv0;
    const float wc1 = dinv1 * dinv1;
    const float wl0 = (t == 0)   ? 0.f : dinv0 * rs3;
    const float wr0 = dinv0 * ((t == 127) ? rs2 : rs3);
    const float wl1 = dinv1 * ((t == 0) ? rs2 : rs3);
    const float wr1 = (t == 127) ? 0.f : dinv1 * rs3;
    const int wprev = (w + 3) & 3;
    const int wnext = (w + 1) & 3;

    // ---------------- stencil 1 + relu ----------------
    {
        if (lane == 31) {
            u64* ea = &edgeA[w * 16];
#pragma unroll
            for (int p = 0; p < 16; p++) ea[p] = pack2(y1[2 * p], y1[2 * p + 1]);
        }
        if (lane == 0) {
            u64* eb = &edgeB[w * 16];
#pragma unroll
            for (int p = 0; p < 16; p++) eb[p] = pack2(y0[2 * p], y0[2 * p + 1]);
        }
        __syncthreads();                                    // barrier 2
#pragma unroll
        for (int f = 0; f < HID; f++) {
            float up = __shfl_up_sync(0xffffffffu, y1[f], 1);
            float pv, nv;
            if (lane == 0) { float a, bb; unpack2(a, bb, edgeA[wprev * 16 + (f >> 1)]); pv = (f & 1) ? bb : a; }
            else pv = up;
            float dn = __shfl_down_sync(0xffffffffu, y0[f], 1);
            if (lane == 31) { float a, bb; unpack2(a, bb, edgeB[wnext * 16 + (f >> 1)]); nv = (f & 1) ? bb : a; }
            else nv = dn;
            float bf = sb1[f];
            float a0 = fmaf(wc0, y0[f], fmaf(wl0, pv,    fmaf(wr0, y1[f], bf)));
            float a1 = fmaf(wc1, y1[f], fmaf(wl1, y0[f], fmaf(wr1, nv,    bf)));
            y0[f] = fmaxf(a0, 0.f);
            y1[f] = fmaxf(a1, 0.f);
        }
    }

    // ---------------- write h1 transposed: hT[k][node-pair], 12-float groups ----
    {
        const int g = t >> 2;
        const int j = (2 * t) & 7;
        u64* dst = (u64*)&hT[g * 12 + j];
#pragma unroll
        for (int k = 0; k < HID; k++)
            dst[k * 192] = pack2(y0[k], y1[k]);
    }
    __syncthreads();                                        // barrier 3

    // ---------------- layer 2 GEMM: warp w -> cols 8w..8w+7, lane -> nodes 8l..8l+7 ----
    const int cw = 8 * w;
    u64 zc[8][4];
#pragma unroll
    for (int j = 0; j < 8; j++)
#pragma unroll
        for (int p = 0; p < 4; p++) zc[j][p] = 0ull;

#pragma unroll 8
    for (int k = 0; k < HID; k++) {
        const ulonglong2 wA = *(const ulonglong2*)&sW2[k * HID + cw];
        const ulonglong2 wB = *(const ulonglong2*)&sW2[k * HID + cw + 4];
        const float* hp = &hT[k * 384 + lane * 12];
        const float4 ha = *(const float4*)hp;
        const float4 hb = *(const float4*)(hp + 4);
#pragma unroll
        for (int j = 0; j < 8; j++) {
            const float hs = (j < 4) ? ((j == 0) ? ha.x : (j == 1) ? ha.y : (j == 2) ? ha.z : ha.w)
                                     : ((j == 4) ? hb.x : (j == 5) ? hb.y : (j == 6) ? hb.z : hb.w);
            const u64 hpk = pack2(hs, hs);
            fma2(zc[j][0], hpk, wA.x);
            fma2(zc[j][1], hpk, wA.y);
            fma2(zc[j][2], hpk, wB.x);
            fma2(zc[j][3], hpk, wB.y);
        }
    }

    // ---------------- stencil 2 + relu + pool (warp-local) ----------------
    u64 pz[4], nz[4], bb2[4];
#pragma unroll
    for (int p = 0; p < 4; p++) {
        pz[p] = __shfl_up_sync(0xffffffffu, zc[7][p], 1);
        nz[p] = __shfl_down_sync(0xffffffffu, zc[0][p], 1);
        bb2[p] = ((const u64*)&sb2[cw])[p];
    }

    const float C13 = 1.f / 3.f;
    const float C12 = 0.5f;
    const float C23 = rs2 * rs3;
    float pool[8];
#pragma unroll
    for (int i = 0; i < 8; i++) pool[i] = 0.f;

#pragma unroll
    for (int j = 0; j < 8; j++) {
        float wcj = C13, wlj = C13, wrj = C13;
        if (lane == 0) {
            if (j == 0) { wcj = C12; wlj = 0.f; wrj = C23; }
            if (j == 1) { wlj = C23; }
        }
        if (lane == 31) {
            if (j == 7) { wcj = C12; wrj = 0.f; wlj = C23; }
            if (j == 6) { wrj = C23; }
        }
        const u64 wcp = pack2(wcj, wcj);
        const u64 wlp = pack2(wlj, wlj);
        const u64 wrp = pack2(wrj, wrj);
#pragma unroll
        for (int p = 0; p < 4; p++) {
            u64 left  = (j == 0) ? pz[p] : zc[j - 1][p];
            u64 right = (j == 7) ? nz[p] : zc[j + 1][p];
            u64 a = bb2[p];
            fma2(a, wcp, zc[j][p]);
            fma2(a, wlp, left);
            fma2(a, wrp, right);
            float r0, r1; unpack2(r0, r1, a);
            pool[2 * p]     += fmaxf(r0, 0.f);
            pool[2 * p + 1] += fmaxf(r1, 0.f);
        }
    }

    // butterfly reduce pool over 32 lanes (packed)
    {
        u64 pp[4];
#pragma unroll
        for (int p = 0; p < 4; p++) pp[p] = pack2(pool[2 * p], pool[2 * p + 1]);
#pragma unroll
        for (int s = 16; s > 0; s >>= 1) {
#pragma unroll
            for (int p = 0; p < 4; p++)
                pp[p] = add2(pp[p], __shfl_xor_sync(0xffffffffu, pp[p], s));
        }
        if (lane == 0) {
#pragma unroll
            for (int p = 0; p < 4; p++) {
                float r0, r1; unpack2(r0, r1, pp[p]);
                pooledS[cw + 2 * p]     = r0 * (1.f / 256.f);
                pooledS[cw + 2 * p + 1] = r1 * (1.f / 256.f);
            }
        }
    }
    __syncthreads();                                        // barrier 4 (last)

    // ---------------- single-warp tail: warp 0 only, shfl-based ----------------
    if (w != 0) return;

    const unsigned FULL = 0xffffffffu;
    const float pl = pooledS[lane];

    // aux layer 1 (per-lane column)
    float a1 = ba1[lane]
             + ph0 * Wa1[0 * HID + lane]
             + ph1 * Wa1[1 * HID + lane]
             + pbs * Wa1[2 * HID + lane]
             + pf0 * Wa1[3 * HID + lane]
             + pf1 * Wa1[4 * HID + lane];
    a1 = fmaxf(a1, 0.f);

    // aux layer 2 + body_emb (shfl broadcasts, no smem)
    float a2 = ba2[lane];
    float be = br[lane];
#pragma unroll
    for (int k = 0; k < HID; k++) {
        float ak = __shfl_sync(FULL, a1, k);
        float pk = __shfl_sync(FULL, pl, k);
        a2 = fmaf(ak, Wa2[k * HID + lane], a2);
        be = fmaf(pk, Wr[k * HID + lane], be);
    }
    a2 = fmaxf(a2, 0.f);

    // combined layer: lane handles cols (lane) and (lane+32)
    float c0 = bc[lane], c1 = bc[32 + lane];
#pragma unroll
    for (int k = 0; k < HID; k++) {
        float bk = __shfl_sync(FULL, be, k);   // cin[k]
        float ak = __shfl_sync(FULL, a2, k);   // cin[32+k]
        c0 = fmaf(bk, Wc[k * FIN + lane],            c0);
        c0 = fmaf(ak, Wc[(32 + k) * FIN + lane],     c0);
        c1 = fmaf(bk, Wc[k * FIN + 32 + lane],       c1);
        c1 = fmaf(ak, Wc[(32 + k) * FIN + 32 + lane],c1);
    }
    c0 = fmaxf(c0, 0.f);   // comb[lane]
    c1 = fmaxf(c1, 0.f);   // comb[32+lane]

    // heads: logits (lanes 0-4), value (lane 5)
    float lg = (lane < 5) ? bp[lane] : 0.f;
    float vv = (lane == 5) ? bv[0] : 0.f;
#pragma unroll
    for (int k = 0; k < HID; k++) {
        float q0 = __shfl_sync(FULL, c0, k);   // comb[k]
        float q1 = __shfl_sync(FULL, c1, k);   // comb[32+k]
        if (lane < 5) {
            lg = fmaf(q0, Wp[k * 5 + lane], lg);
            lg = fmaf(q1, Wp[(32 + k) * 5 + lane], lg);
        } else if (lane == 5) {
            vv = fmaf(q0, Wv[k], vv);
            vv = fmaf(q1, Wv[32 + k], vv);
        }
    }
    if (lane < 5)       out[b * 5 + lane] = lg;     // logits [B,5]
    else if (lane == 5) out[B_G * 5 + b] = vv;      // value [B]
}

extern "C" void kernel_launch(void* const* d_in, const int* in_sizes, int n_in,
                              void* d_out, int out_size) {
    const float* x          = (const float*)d_in[0];
    const float* heads      = (const float*)d_in[1];
    const float* body_sizes = (const float*)d_in[2];
    const float* fruits     = (const float*)d_in[3];
    const float* W1  = (const float*)d_in[4];
    const float* b1  = (const float*)d_in[5];
    const float* W2  = (const float*)d_in[6];
    const float* b2  = (const float*)d_in[7];
    const float* Wr  = (const float*)d_in[8];
    const float* br  = (const float*)d_in[9];
    const float* Wa1 = (const float*)d_in[10];
    const float* ba1 = (const float*)d_in[11];
    const float* Wa2 = (const float*)d_in[12];
    const float* ba2 = (const float*)d_in[13];
    const float* Wc  = (const float*)d_in[14];
    const float* bc  = (const float*)d_in[15];
    const float* Wp  = (const float*)d_in[16];
    const float* bp  = (const float*)d_in[17];
    const float* Wv  = (const float*)d_in[18];
    const float* bv  = (const float*)d_in[19];
    // d_in[20] = edge_index, d_in[21] = batch_ids: static chain, unused

    cudaFuncSetAttribute(snake_kernel, cudaFuncAttributeMaxDynamicSharedMemorySize, SMEM_TOTAL);
    float* out = (float*)d_out;
    snake_kernel<<<B_G, 128, SMEM_TOTAL>>>(x, heads, body_sizes, fruits,
                               W1, b1, W2, b2, Wr, br,
                               Wa1, ba1, Wa2, ba2, Wc, bc,
                               Wp, bp, Wv, bv, out);
}

// round 9
// speedup vs baseline: 1.4258x; 1.4258x over previous
#include <cuda_runtime.h>

#define B_G 4096
#define HID 32
#define FIN 64

typedef unsigned long long u64;

__device__ __forceinline__ u64 pack2(float a, float b) {
    u64 r; asm("mov.b64 %0, {%1, %2};" : "=l"(r) : "f"(a), "f"(b)); return r;
}
__device__ __forceinline__ void unpack2(float& a, float& b, u64 v) {
    asm("mov.b64 {%0, %1}, %2;" : "=f"(a), "=f"(b) : "l"(v));
}
__device__ __forceinline__ void fma2(u64& d, u64 a, u64 b) {
    asm("fma.rn.f32x2 %0, %1, %2, %0;" : "+l"(d) : "l"(a), "l"(b));
}
__device__ __forceinline__ u64 mul2(u64 a, u64 b) {
    u64 r; asm("mul.rn.f32x2 %0, %1, %2;" : "=l"(r) : "l"(a), "l"(b)); return r;
}
__device__ __forceinline__ u64 add2(u64 a, u64 b) {
    u64 r; asm("add.rn.f32x2 %0, %1, %2;" : "=l"(r) : "l"(a), "l"(b)); return r;
}

// dynamic smem layout (bytes)
#define HT_OFF     0         // hT: 32 rows x 384 floats (12-float lane groups) = 49152
#define W2_OFF     49152     // 4 KB
#define W1_OFF     53248     // 256 B
#define B1_OFF     53504     // 128 B
#define B2_OFF     53632     // 128 B
#define EA_OFF     53760     // 4 warps x 16 u64 = 512 B
#define EB_OFF     54272     // 512 B
#define PL_OFF     54784     // pooled, 128 B
#define CI_OFF     54912     // cin, 256 B
#define CB_OFF     55168     // comb, 256 B
#define SMEM_TOTAL 55424

__global__ __launch_bounds__(128, 4)
void snake_kernel(const float* __restrict__ x,
                  const float* __restrict__ heads,
                  const float* __restrict__ body_sizes,
                  const float* __restrict__ fruits,
                  const float* __restrict__ W1, const float* __restrict__ b1,
                  const float* __restrict__ W2, const float* __restrict__ b2,
                  const float* __restrict__ Wr, const float* __restrict__ br,
                  const float* __restrict__ Wa1, const float* __restrict__ ba1,
                  const float* __restrict__ Wa2, const float* __restrict__ ba2,
                  const float* __restrict__ Wc, const float* __restrict__ bc,
                  const float* __restrict__ Wp, const float* __restrict__ bp,
                  const float* __restrict__ Wv, const float* __restrict__ bv,
                  float* __restrict__ out)
{
    extern __shared__ __align__(16) char smem[];
    float* hT   = (float*)(smem + HT_OFF);
    float* sW2  = (float*)(smem + W2_OFF);
    float* sW1  = (float*)(smem + W1_OFF);
    float* sb1  = (float*)(smem + B1_OFF);
    float* sb2  = (float*)(smem + B2_OFF);
    u64*  edgeA = (u64*)(smem + EA_OFF);     // [warp][16]
    u64*  edgeB = (u64*)(smem + EB_OFF);
    float* pooledS = (float*)(smem + PL_OFF);
    float* cinS    = (float*)(smem + CI_OFF);
    float* combS   = (float*)(smem + CB_OFF);

    const int b = blockIdx.x;
    const int t = threadIdx.x;
    const int lane = t & 31;
    const int w = t >> 5;

    // ---- weight staging ----
    ((float4*)sW2)[t] = ((const float4*)W2)[t];
    ((float4*)sW2)[t + 128] = ((const float4*)W2)[t + 128];
    if (t < 16) ((float4*)sW1)[t] = ((const float4*)W1)[t];
    else if (t < 24) ((float4*)sb1)[t - 16] = ((const float4*)b1)[t - 16];
    else if (t < 32) ((float4*)sb2)[t - 24] = ((const float4*)b2)[t - 24];

    const float4 xv = ((const float4*)x)[b * 128 + t];
    __syncthreads();                                        // barrier 1

    // ---------------- layer 1: y = x @ W1 (nodes 2t, 2t+1) ----------------
    float y0[HID], y1[HID];
    {
        const u64* w1a = (const u64*)sW1;
        const u64* w1b = (const u64*)(sW1 + HID);
        const u64 xa0 = pack2(xv.x, xv.x), xb0 = pack2(xv.y, xv.y);
        const u64 xa1 = pack2(xv.z, xv.z), xb1 = pack2(xv.w, xv.w);
#pragma unroll
        for (int p = 0; p < 16; p++) {
            const u64 wA = w1a[p], wB = w1b[p];
            u64 v0 = mul2(xa0, wA); fma2(v0, xb0, wB);
            u64 v1 = mul2(xa1, wA); fma2(v1, xb1, wB);
            unpack2(y0[2 * p], y0[2 * p + 1], v0);
            unpack2(y1[2 * p], y1[2 * p + 1], v1);
        }
    }

    // ---- stencil 1 weights (nodes 2t, 2t+1; L=256) ----
    const float rs2 = 0.70710678118654752440f;
    const float rs3 = 0.57735026918962576451f;
    const float dinv0 = (t == 0)   ? rs2 : rs3;
    const float dinv1 = (t == 127) ? rs2 : rs3;
    const float wc0 = dinv0 * dinv0;
    const float wc1 = dinv1 * dinv1;
    const float wl0 = (t == 0)   ? 0.f : dinv0 * rs3;
    const float wr0 = dinv0 * ((t == 127) ? rs2 : rs3);
    const float wl1 = dinv1 * ((t == 0) ? rs2 : rs3);
    const float wr1 = (t == 127) ? 0.f : dinv1 * rs3;
    const int wprev = (w + 3) & 3;
    const int wnext = (w + 1) & 3;

    // ---------------- stencil 1 + relu ----------------
    {
        if (lane == 31) {
            u64* ea = &edgeA[w * 16];
#pragma unroll
            for (int p = 0; p < 16; p++) ea[p] = pack2(y1[2 * p], y1[2 * p + 1]);
        }
        if (lane == 0) {
            u64* eb = &edgeB[w * 16];
#pragma unroll
            for (int p = 0; p < 16; p++) eb[p] = pack2(y0[2 * p], y0[2 * p + 1]);
        }
        __syncthreads();                                    // barrier 2
#pragma unroll
        for (int f = 0; f < HID; f++) {
            float up = __shfl_up_sync(0xffffffffu, y1[f], 1);
            float pv, nv;
            if (lane == 0) { float a, bb; unpack2(a, bb, edgeA[wprev * 16 + (f >> 1)]); pv = (f & 1) ? bb : a; }
            else pv = up;
            float dn = __shfl_down_sync(0xffffffffu, y0[f], 1);
            if (lane == 31) { float a, bb; unpack2(a, bb, edgeB[wnext * 16 + (f >> 1)]); nv = (f & 1) ? bb : a; }
            else nv = dn;
            float bf = sb1[f];
            float a0 = fmaf(wc0, y0[f], fmaf(wl0, pv,    fmaf(wr0, y1[f], bf)));
            float a1 = fmaf(wc1, y1[f], fmaf(wl1, y0[f], fmaf(wr1, nv,    bf)));
            y0[f] = fmaxf(a0, 0.f);
            y1[f] = fmaxf(a1, 0.f);
        }
    }

    // ---------------- write h1 transposed: hT[k][node-pair], 12-float groups ----
    {
        const int g = t >> 2;
        const int j = (2 * t) & 7;
        u64* dst = (u64*)&hT[g * 12 + j];
#pragma unroll
        for (int k = 0; k < HID; k++)
            dst[k * 192] = pack2(y0[k], y1[k]);
    }
    __syncthreads();                                        // barrier 3

    // ---------------- layer 2 GEMM: warp w -> cols 8w..8w+7, lane -> nodes 8l..8l+7 ----
    const int cw = 8 * w;
    u64 zc[8][4];
#pragma unroll
    for (int j = 0; j < 8; j++)
#pragma unroll
        for (int p = 0; p < 4; p++) zc[j][p] = 0ull;

#pragma unroll 8
    for (int k = 0; k < HID; k++) {
        const ulonglong2 wA = *(const ulonglong2*)&sW2[k * HID + cw];
        const ulonglong2 wB = *(const ulonglong2*)&sW2[k * HID + cw + 4];
        const float* hp = &hT[k * 384 + lane * 12];
        const float4 ha = *(const float4*)hp;
        const float4 hb = *(const float4*)(hp + 4);
#pragma unroll
        for (int j = 0; j < 8; j++) {
            const float hs = (j < 4) ? ((j == 0) ? ha.x : (j == 1) ? ha.y : (j == 2) ? ha.z : ha.w)
                                     : ((j == 4) ? hb.x : (j == 5) ? hb.y : (j == 6) ? hb.z : hb.w);
            const u64 hpk = pack2(hs, hs);
            fma2(zc[j][0], hpk, wA.x);
            fma2(zc[j][1], hpk, wA.y);
            fma2(zc[j][2], hpk, wB.x);
            fma2(zc[j][3], hpk, wB.y);
        }
    }

    // ---------------- stencil 2 + relu + pool (warp-local) ----------------
    u64 pz[4], nz[4], bb2[4];
#pragma unroll
    for (int p = 0; p < 4; p++) {
        pz[p] = __shfl_up_sync(0xffffffffu, zc[7][p], 1);
        nz[p] = __shfl_down_sync(0xffffffffu, zc[0][p], 1);
        bb2[p] = ((const u64*)&sb2[cw])[p];
    }

    const float C13 = 1.f / 3.f;
    const float C12 = 0.5f;
    const float C23 = rs2 * rs3;
    float pool[8];
#pragma unroll
    for (int i = 0; i < 8; i++) pool[i] = 0.f;

#pragma unroll
    for (int j = 0; j < 8; j++) {
        float wcj = C13, wlj = C13, wrj = C13;
        if (lane == 0) {
            if (j == 0) { wcj = C12; wlj = 0.f; wrj = C23; }
            if (j == 1) { wlj = C23; }
        }
        if (lane == 31) {
            if (j == 7) { wcj = C12; wrj = 0.f; wlj = C23; }
            if (j == 6) { wrj = C23; }
        }
        const u64 wcp = pack2(wcj, wcj);
        const u64 wlp = pack2(wlj, wlj);
        const u64 wrp = pack2(wrj, wrj);
#pragma unroll
        for (int p = 0; p < 4; p++) {
            u64 left  = (j == 0) ? pz[p] : zc[j - 1][p];
            u64 right = (j == 7) ? nz[p] : zc[j + 1][p];
            u64 a = bb2[p];
            fma2(a, wcp, zc[j][p]);
            fma2(a, wlp, left);
            fma2(a, wrp, right);
            float r0, r1; unpack2(r0, r1, a);
            pool[2 * p]     += fmaxf(r0, 0.f);
            pool[2 * p + 1] += fmaxf(r1, 0.f);
        }
    }

    // butterfly reduce pool over 32 lanes (packed)
    {
        u64 pp[4];
#pragma unroll
        for (int p = 0; p < 4; p++) pp[p] = pack2(pool[2 * p], pool[2 * p + 1]);
#pragma unroll
        for (int s = 16; s > 0; s >>= 1) {
#pragma unroll
            for (int p = 0; p < 4; p++)
                pp[p] = add2(pp[p], __shfl_xor_sync(0xffffffffu, pp[p], s));
        }
        if (lane == 0) {
#pragma unroll
            for (int p = 0; p < 4; p++) {
                float r0, r1; unpack2(r0, r1, pp[p]);
                pooledS[cw + 2 * p]     = r0 * (1.f / 256.f);
                pooledS[cw + 2 * p + 1] = r1 * (1.f / 256.f);
            }
        }
    }
    __syncthreads();                                        // barrier 4

    // ---------------- tail: warp 0 does aux1+aux2+body_emb in ONE segment ----
    if (t < HID) {
        const unsigned FULL = 0xffffffffu;
        const float h0 = heads[2 * b], h1v = heads[2 * b + 1];
        const float bs = body_sizes[b];
        const float fr0 = fruits[2 * b], fr1 = fruits[2 * b + 1];
        float a1 = ba1[t]
                 + h0  * Wa1[0 * HID + t]
                 + h1v * Wa1[1 * HID + t]
                 + bs  * Wa1[2 * HID + t]
                 + fr0 * Wa1[3 * HID + t]
                 + fr1 * Wa1[4 * HID + t];
        a1 = fmaxf(a1, 0.f);

        const float pl = pooledS[t];
        float a2 = ba2[t];
        float be = br[t];
#pragma unroll
        for (int k = 0; k < HID; k++) {
            float ak = __shfl_sync(FULL, a1, k);
            float pk = __shfl_sync(FULL, pl, k);
            a2 = fmaf(ak, Wa2[k * HID + t], a2);
            be = fmaf(pk, Wr[k * HID + t], be);
        }
        a2 = fmaxf(a2, 0.f);
        cinS[t] = be;          // body_emb
        cinS[HID + t] = a2;    // aux
    }
    __syncthreads();                                        // barrier 5

    if (t < FIN) {
        float c = bc[t];
#pragma unroll
        for (int k = 0; k < FIN; k++) c += cinS[k] * Wc[k * FIN + t];
        combS[t] = fmaxf(c, 0.f);
    }
    __syncthreads();                                        // barrier 6

    if (t < 5) {
        float lg = bp[t];
#pragma unroll
        for (int k = 0; k < FIN; k++) lg += combS[k] * Wp[k * 5 + t];
        out[b * 5 + t] = lg;                      // logits [B,5]
    } else if (t == 5) {
        float v = bv[0];
#pragma unroll
        for (int k = 0; k < FIN; k++) v += combS[k] * Wv[k];
        out[B_G * 5 + b] = v;                     // value [B]
    }
}

extern "C" void kernel_launch(void* const* d_in, const int* in_sizes, int n_in,
                              void* d_out, int out_size) {
    const float* x          = (const float*)d_in[0];
    const float* heads      = (const float*)d_in[1];
    const float* body_sizes = (const float*)d_in[2];
    const float* fruits     = (const float*)d_in[3];
    const float* W1  = (const float*)d_in[4];
    const float* b1  = (const float*)d_in[5];
    const float* W2  = (const float*)d_in[6];
    const float* b2  = (const float*)d_in[7];
    const float* Wr  = (const float*)d_in[8];
    const float* br  = (const float*)d_in[9];
    const float* Wa1 = (const float*)d_in[10];
    const float* ba1 = (const float*)d_in[11];
    const float* Wa2 = (const float*)d_in[12];
    const float* ba2 = (const float*)d_in[13];
    const float* Wc  = (const float*)d_in[14];
    const float* bc  = (const float*)d_in[15];
    const float* Wp  = (const float*)d_in[16];
    const float* bp  = (const float*)d_in[17];
    const float* Wv  = (const float*)d_in[18];
    const float* bv  = (const float*)d_in[19];
    // d_in[20] = edge_index, d_in[21] = batch_ids: static chain, unused

    cudaFuncSetAttribute(snake_kernel, cudaFuncAttributeMaxDynamicSharedMemorySize, SMEM_TOTAL);
    float* out = (float*)d_out;
    snake_kernel<<<B_G, 128, SMEM_TOTAL>>>(x, heads, body_sizes, fruits,
                               W1, b1, W2, b2, Wr, br,
                               Wa1, ba1, Wa2, ba2, Wc, bc,
                               Wp, bp, Wv, bv, out);
}

// round 13
// speedup vs baseline: 1.5274x; 1.0713x over previous
#include <cuda_runtime.h>

#define B_G 4096
#define HID 32
#define FIN 64

typedef unsigned long long u64;

__device__ __forceinline__ u64 pack2(float a, float b) {
    u64 r; asm("mov.b64 %0, {%1, %2};" : "=l"(r) : "f"(a), "f"(b)); return r;
}
__device__ __forceinline__ void unpack2(float& a, float& b, u64 v) {
    asm("mov.b64 {%0, %1}, %2;" : "=f"(a), "=f"(b) : "l"(v));
}
__device__ __forceinline__ void fma2(u64& d, u64 a, u64 b) {
    asm("fma.rn.f32x2 %0, %1, %2, %0;" : "+l"(d) : "l"(a), "l"(b));
}
__device__ __forceinline__ u64 mul2(u64 a, u64 b) {
    u64 r; asm("mul.rn.f32x2 %0, %1, %2;" : "=l"(r) : "l"(a), "l"(b)); return r;
}
__device__ __forceinline__ u64 add2(u64 a, u64 b) {
    u64 r; asm("add.rn.f32x2 %0, %1, %2;" : "=l"(r) : "l"(a), "l"(b)); return r;
}

// hT row: 32 lanes x 8 floats with 4-float pad every 4 lanes = 288 floats (1152 B)
#define HTROW 288

// dynamic smem layout (bytes)
#define HT_OFF     0         // 32 * 1152 = 36864
#define W2_OFF     36864     // 4 KB
#define W1_OFF     40960     // 256 B
#define B1_OFF     41216     // 128 B
#define B2_OFF     41344     // 128 B
#define EA_OFF     41472     // 512 B
#define EB_OFF     41984     // 512 B
#define PL_OFF     42496     // 128 B
#define CI_OFF     42624     // 256 B
#define CB_OFF     42880     // 256 B
#define SMEM_TOTAL 43136

__global__ __launch_bounds__(128, 5)
void snake_kernel(const float* __restrict__ x,
                  const float* __restrict__ heads,
                  const float* __restrict__ body_sizes,
                  const float* __restrict__ fruits,
                  const float* __restrict__ W1, const float* __restrict__ b1,
                  const float* __restrict__ W2, const float* __restrict__ b2,
                  const float* __restrict__ Wr, const float* __restrict__ br,
                  const float* __restrict__ Wa1, const float* __restrict__ ba1,
                  const float* __restrict__ Wa2, const float* __restrict__ ba2,
                  const float* __restrict__ Wc, const float* __restrict__ bc,
                  const float* __restrict__ Wp, const float* __restrict__ bp,
                  const float* __restrict__ Wv, const float* __restrict__ bv,
                  float* __restrict__ out)
{
    extern __shared__ __align__(16) char smem[];
    float* hT   = (float*)(smem + HT_OFF);
    float* sW2  = (float*)(smem + W2_OFF);
    float* sW1  = (float*)(smem + W1_OFF);
    float* sb1  = (float*)(smem + B1_OFF);
    float* sb2  = (float*)(smem + B2_OFF);
    u64*  edgeA = (u64*)(smem + EA_OFF);     // [warp][16]
    u64*  edgeB = (u64*)(smem + EB_OFF);
    float* pooledS = (float*)(smem + PL_OFF);
    float* cinS    = (float*)(smem + CI_OFF);
    float* combS   = (float*)(smem + CB_OFF);

    const int b = blockIdx.x;
    const int t = threadIdx.x;
    const int lane = t & 31;
    const int w = t >> 5;

    // ---- weight staging ----
    ((float4*)sW2)[t] = ((const float4*)W2)[t];
    ((float4*)sW2)[t + 128] = ((const float4*)W2)[t + 128];
    if (t < 16) ((float4*)sW1)[t] = ((const float4*)W1)[t];
    else if (t < 24) ((float4*)sb1)[t - 16] = ((const float4*)b1)[t - 16];
    else if (t < 32) ((float4*)sb2)[t - 24] = ((const float4*)b2)[t - 24];

    const float4 xv = ((const float4*)x)[b * 128 + t];
    __syncthreads();                                        // barrier 1

    // ---------------- layer 1: y = x @ W1 (nodes 2t, 2t+1) ----------------
    float y0[HID], y1[HID];
    {
        const u64* w1a = (const u64*)sW1;
        const u64* w1b = (const u64*)(sW1 + HID);
        const u64 xa0 = pack2(xv.x, xv.x), xb0 = pack2(xv.y, xv.y);
        const u64 xa1 = pack2(xv.z, xv.z), xb1 = pack2(xv.w, xv.w);
#pragma unroll
        for (int p = 0; p < 16; p++) {
            const u64 wA = w1a[p], wB = w1b[p];
            u64 v0 = mul2(xa0, wA); fma2(v0, xb0, wB);
            u64 v1 = mul2(xa1, wA); fma2(v1, xb1, wB);
            unpack2(y0[2 * p], y0[2 * p + 1], v0);
            unpack2(y1[2 * p], y1[2 * p + 1], v1);
        }
    }

    // ---- stencil 1 weights (nodes 2t, 2t+1; L=256) ----
    const float rs2 = 0.70710678118654752440f;
    const float rs3 = 0.57735026918962576451f;
    const float dinv0 = (t == 0)   ? rs2 : rs3;
    const float dinv1 = (t == 127) ? rs2 : rs3;
    const float wc0 = dinv0 * dinv0;
    const float wc1 = dinv1 * dinv1;
    const float wl0 = (t == 0)   ? 0.f : dinv0 * rs3;
    const float wr0 = dinv0 * ((t == 127) ? rs2 : rs3);
    const float wl1 = dinv1 * ((t == 0) ? rs2 : rs3);
    const float wr1 = (t == 127) ? 0.f : dinv1 * rs3;
    const int wprev = (w + 3) & 3;
    const int wnext = (w + 1) & 3;

    // ---------------- stencil 1 + relu ----------------
    {
        if (lane == 31) {
            u64* ea = &edgeA[w * 16];
#pragma unroll
            for (int p = 0; p < 16; p++) ea[p] = pack2(y1[2 * p], y1[2 * p + 1]);
        }
        if (lane == 0) {
            u64* eb = &edgeB[w * 16];
#pragma unroll
            for (int p = 0; p < 16; p++) eb[p] = pack2(y0[2 * p], y0[2 * p + 1]);
        }
        __syncthreads();                                    // barrier 2
#pragma unroll
        for (int f = 0; f < HID; f++) {
            float up = __shfl_up_sync(0xffffffffu, y1[f], 1);
            float pv, nv;
            if (lane == 0) { float a, bb; unpack2(a, bb, edgeA[wprev * 16 + (f >> 1)]); pv = (f & 1) ? bb : a; }
            else pv = up;
            float dn = __shfl_down_sync(0xffffffffu, y0[f], 1);
            if (lane == 31) { float a, bb; unpack2(a, bb, edgeB[wnext * 16 + (f >> 1)]); nv = (f & 1) ? bb : a; }
            else nv = dn;
            float bf = sb1[f];
            float a0 = fmaf(wc0, y0[f], fmaf(wl0, pv,    fmaf(wr0, y1[f], bf)));
            float a1 = fmaf(wc1, y1[f], fmaf(wl1, y0[f], fmaf(wr1, nv,    bf)));
            y0[f] = fmaxf(a0, 0.f);
            y1[f] = fmaxf(a1, 0.f);
        }
    }

    // -------- write h1 transposed: hT[k][node], dense layout w/ 4-float pad per 4 lanes --------
    // node m -> float offset m + 4*(m/32); thread t holds nodes 2t,2t+1 (one u64)
    {
        const int slot = t + 2 * (t >> 4);   // u64 slot: (2t + 4*(2t/32)) / 2
        u64* dst = (u64*)hT + slot;
#pragma unroll
        for (int k = 0; k < HID; k++)
            dst[k * (HTROW / 2)] = pack2(y0[k], y1[k]);
    }
    __syncthreads();                                        // barrier 3

    // ---------------- layer 2 GEMM: warp w -> cols 8w..8w+7, lane -> nodes 8l..8l+7 ----
    const int cw = 8 * w;
    const int hoff = lane * 8 + (lane >> 2) * 4;
    u64 zc[8][4];
#pragma unroll
    for (int j = 0; j < 8; j++)
#pragma unroll
        for (int p = 0; p < 4; p++) zc[j][p] = 0ull;

#pragma unroll 8
    for (int k = 0; k < HID; k++) {
        const ulonglong2 wA = *(const ulonglong2*)&sW2[k * HID + cw];
        const ulonglong2 wB = *(const ulonglong2*)&sW2[k * HID + cw + 4];
        const float* hp = &hT[k * HTROW + hoff];
        const float4 ha = *(const float4*)hp;
        const float4 hb = *(const float4*)(hp + 4);
#pragma unroll
        for (int j = 0; j < 8; j++) {
            const float hs = (j < 4) ? ((j == 0) ? ha.x : (j == 1) ? ha.y : (j == 2) ? ha.z : ha.w)
                                     : ((j == 4) ? hb.x : (j == 5) ? hb.y : (j == 6) ? hb.z : hb.w);
            const u64 hpk = pack2(hs, hs);
            fma2(zc[j][0], hpk, wA.x);
            fma2(zc[j][1], hpk, wA.y);
            fma2(zc[j][2], hpk, wB.x);
            fma2(zc[j][3], hpk, wB.y);
        }
    }

    // ---------------- stencil 2 + relu + pool (warp-local) ----------------
    u64 pz[4], nz[4], bb2[4];
#pragma unroll
    for (int p = 0; p < 4; p++) {
        pz[p] = __shfl_up_sync(0xffffffffu, zc[7][p], 1);
        nz[p] = __shfl_down_sync(0xffffffffu, zc[0][p], 1);
        bb2[p] = ((const u64*)&sb2[cw])[p];
    }

    const float C13 = 1.f / 3.f;
    const float C12 = 0.5f;
    const float C23 = rs2 * rs3;
    float pool[8];
#pragma unroll
    for (int i = 0; i < 8; i++) pool[i] = 0.f;

#pragma unroll
    for (int j = 0; j < 8; j++) {
        float wcj = C13, wlj = C13, wrj = C13;
        if (lane == 0) {
            if (j == 0) { wcj = C12; wlj = 0.f; wrj = C23; }
            if (j == 1) { wlj = C23; }
        }
        if (lane == 31) {
            if (j == 7) { wcj = C12; wrj = 0.f; wlj = C23; }
            if (j == 6) { wrj = C23; }
        }
        const u64 wcp = pack2(wcj, wcj);
        const u64 wlp = pack2(wlj, wlj);
        const u64 wrp = pack2(wrj, wrj);
#pragma unroll
        for (int p = 0; p < 4; p++) {
            u64 left  = (j == 0) ? pz[p] : zc[j - 1][p];
            u64 right = (j == 7) ? nz[p] : zc[j + 1][p];
            u64 a = bb2[p];
            fma2(a, wcp, zc[j][p]);
            fma2(a, wlp, left);
            fma2(a, wrp, right);
            float r0, r1; unpack2(r0, r1, a);
            pool[2 * p]     += fmaxf(r0, 0.f);
            pool[2 * p + 1] += fmaxf(r1, 0.f);
        }
    }

    // butterfly reduce pool over 32 lanes (packed)
    {
        u64 pp[4];
#pragma unroll
        for (int p = 0; p < 4; p++) pp[p] = pack2(pool[2 * p], pool[2 * p + 1]);
#pragma unroll
        for (int s = 16; s > 0; s >>= 1) {
#pragma unroll
            for (int p = 0; p < 4; p++)
                pp[p] = add2(pp[p], __shfl_xor_sync(0xffffffffu, pp[p], s));
        }
        if (lane == 0) {
#pragma unroll
            for (int p = 0; p < 4; p++) {
                float r0, r1; unpack2(r0, r1, pp[p]);
                pooledS[cw + 2 * p]     = r0 * (1.f / 256.f);
                pooledS[cw + 2 * p + 1] = r1 * (1.f / 256.f);
            }
        }
    }
    __syncthreads();                                        // barrier 4

    // ---------------- tail: warp 0 does aux1+aux2+body_emb in ONE segment ----
    if (t < HID) {
        const unsigned FULL = 0xffffffffu;
        const float h0 = heads[2 * b], h1v = heads[2 * b + 1];
        const float bs = body_sizes[b];
        const float fr0 = fruits[2 * b], fr1 = fruits[2 * b + 1];
        float a1 = ba1[t]
                 + h0  * Wa1[0 * HID + t]
                 + h1v * Wa1[1 * HID + t]
                 + bs  * Wa1[2 * HID + t]
                 + fr0 * Wa1[3 * HID + t]
                 + fr1 * Wa1[4 * HID + t];
        a1 = fmaxf(a1, 0.f);

        const float pl = pooledS[t];
        float a2 = ba2[t];
        float be = br[t];
#pragma unroll
        for (int k = 0; k < HID; k++) {
            float ak = __shfl_sync(FULL, a1, k);
            float pk = __shfl_sync(FULL, pl, k);
            a2 = fmaf(ak, Wa2[k * HID + t], a2);
            be = fmaf(pk, Wr[k * HID + t], be);
        }
        a2 = fmaxf(a2, 0.f);
        cinS[t] = be;          // body_emb
        cinS[HID + t] = a2;    // aux
    }
    __syncthreads();                                        // barrier 5

    if (t < FIN) {
        float c = bc[t];
#pragma unroll
        for (int k = 0; k < FIN; k++) c += cinS[k] * Wc[k * FIN + t];
        combS[t] = fmaxf(c, 0.f);
    }
    __syncthreads();                                        // barrier 6

    if (t < 5) {
        float lg = bp[t];
#pragma unroll
        for (int k = 0; k < FIN; k++) lg += combS[k] * Wp[k * 5 + t];
        out[b * 5 + t] = lg;                      // logits [B,5]
    } else if (t == 5) {
        float v = bv[0];
#pragma unroll
        for (int k = 0; k < FIN; k++) v += combS[k] * Wv[k];
        out[B_G * 5 + b] = v;                     // value [B]
    }
}

extern "C" void kernel_launch(void* const* d_in, const int* in_sizes, int n_in,
                              void* d_out, int out_size) {
    const float* x          = (const float*)d_in[0];
    const float* heads      = (const float*)d_in[1];
    const float* body_sizes = (const float*)d_in[2];
    const float* fruits     = (const float*)d_in[3];
    const float* W1  = (const float*)d_in[4];
    const float* b1  = (const float*)d_in[5];
    const float* W2  = (const float*)d_in[6];
    const float* b2  = (const float*)d_in[7];
    const float* Wr  = (const float*)d_in[8];
    const float* br  = (const float*)d_in[9];
    const float* Wa1 = (const float*)d_in[10];
    const float* ba1 = (const float*)d_in[11];
    const float* Wa2 = (const float*)d_in[12];
    const float* ba2 = (const float*)d_in[13];
    const float* Wc  = (const float*)d_in[14];
    const float* bc  = (const float*)d_in[15];
    const float* Wp  = (const float*)d_in[16];
    const float* bp  = (const float*)d_in[17];
    const float* Wv  = (const float*)d_in[18];
    const float* bv  = (const float*)d_in[19];
    // d_in[20] = edge_index, d_in[21] = batch_ids: static chain, unused

    cudaFuncSetAttribute(snake_kernel, cudaFuncAttributeMaxDynamicSharedMemorySize, SMEM_TOTAL);
    float* out = (float*)d_out;
    snake_kernel<<<B_G, 128, SMEM_TOTAL>>>(x, heads, body_sizes, fruits,
                               W1, b1, W2, b2, Wr, br,
                               Wa1, ba1, Wa2, ba2, Wc, bc,
                               Wp, bp, Wv, bv, out);
}